// round 5
// baseline (speedup 1.0000x reference)
#include <cuda_runtime.h>
#include <cstdint>
#include <cstddef>

// ---------------------------------------------------------------------------
// BinaryDense: out[N,F] = inputs[N,D] @ w_bin[D,F],  N=2^20, D=F=128
// w_bin = 2*bernoulli(threefry2x32(key(seed)), hard_sigmoid(W)) - 1
// RNG: JAX *partitionable* threefry (modern default): per-element counter
//      (hi,lo) = (0, idx), 32-bit draw = out0 ^ out1.
// Legacy-pipe tf32 mma.sync GEMM (tcgen05 unavailable: harness targets sm_103).
// Persistent CTAs, cp.async double-buffered A, B resident in SMEM.
// ---------------------------------------------------------------------------

#define PAD        132                      // floats per padded SMEM row
#define ABUF_FLTS  (128 * PAD)              // 16896 floats = 67584 B
#define SMEM_TOTAL (3 * ABUF_FLTS * 4)      // A0 + A1 + B = 202752 B

// w_bin image, [f][d] row-major, values exactly +1.0f / -1.0f
static __device__ float g_B[16384];

// --------------------------- w_bin precompute ------------------------------
// Partitionable threefry2x32 (JAX >= 0.4.36 default):
//   key  = (0, seed)
//   ctr  = (uint64)flat_idx  ->  x0 = idx>>32 = 0,  x1 = idx (lo 32)
//   bits = out0 ^ out1                      (32-bit draw)
//   u    = bitcast((bits>>9)|0x3f800000) - 1
//   w_bin= (u < clip((w+1)*0.5,0,1)) ? +1 : -1     (sign(w) if !is_training)

__device__ __forceinline__ uint32_t rotl32(uint32_t x, int r) {
    return (x << r) | (x >> (32 - r));
}

__global__ void wbin_kernel(const float* __restrict__ w,
                            const int* __restrict__ seedp,
                            const int* __restrict__ trainp) {
    int idx = blockIdx.x * blockDim.x + threadIdx.x;   // (d, f) row-major
    int d = idx >> 7;
    int f = idx & 127;
    float wv = w[idx];
    float bin;
    if (*trainp) {
        uint32_t k0 = 0u, k1 = (uint32_t)(*seedp);
        uint32_t x0 = 0u;                  // counter hi word (idx < 2^32)
        uint32_t x1 = (uint32_t)idx;       // counter lo word
        uint32_t ks[3] = { k0, k1, k0 ^ k1 ^ 0x1BD11BDAu };
        x0 += ks[0];
        x1 += ks[1];
        const int rot[2][4] = { {13, 15, 26, 6}, {17, 29, 16, 24} };
        #pragma unroll
        for (int i = 0; i < 5; i++) {
            #pragma unroll
            for (int j = 0; j < 4; j++) {
                x0 += x1;
                x1 = rotl32(x1, rot[i & 1][j]);
                x1 ^= x0;
            }
            x0 += ks[(i + 1) % 3];
            x1 += ks[(i + 2) % 3] + (uint32_t)(i + 1);
        }
        uint32_t bits = x0 ^ x1;           // partitionable 32-bit fold
        float u = __uint_as_float((bits >> 9) | 0x3f800000u) - 1.0f;
        float p = fminf(fmaxf((wv + 1.0f) * 0.5f, 0.0f), 1.0f);
        bin = (u < p) ? 1.0f : -1.0f;
    } else {
        bin = (wv > 0.0f) ? 1.0f : -1.0f;
    }
    g_B[f * 128 + d] = bin;   // transposed: [f][d]
}

// ------------------------------- GEMM --------------------------------------

__device__ __forceinline__ uint32_t smem_u32(const void* p) {
    uint32_t a;
    asm("{ .reg .u64 t; cvta.to.shared.u64 t, %1; cvt.u32.u64 %0, t; }"
        : "=r"(a) : "l"(p));
    return a;
}

__device__ __forceinline__ uint32_t f2tf32(float x) {
    uint32_t r;
    asm("cvt.rna.tf32.f32 %0, %1;" : "=r"(r) : "f"(x));
    return r;
}

__device__ __forceinline__ void mma_tf32(float* d, uint32_t a0, uint32_t a1,
                                         uint32_t a2, uint32_t a3,
                                         uint32_t b0, uint32_t b1) {
    asm volatile(
        "mma.sync.aligned.m16n8k8.row.col.f32.tf32.tf32.f32 "
        "{%0,%1,%2,%3}, {%4,%5,%6,%7}, {%8,%9}, {%0,%1,%2,%3};"
        : "+f"(d[0]), "+f"(d[1]), "+f"(d[2]), "+f"(d[3])
        : "r"(a0), "r"(a1), "r"(a2), "r"(a3), "r"(b0), "r"(b1));
}

// One 128x128-float A tile (64 KB) -> padded SMEM buffer, 16B cp.async chunks.
__device__ __forceinline__ void issue_a(uint32_t sbase, const float* __restrict__ A,
                                        int tile, int tid) {
    const char* g = (const char*)(A + (size_t)tile * 16384);
    #pragma unroll
    for (int j = 0; j < 16; j++) {
        int id = tid + j * 256;            // 4096 chunks of 16 B
        int m  = id >> 5;
        int k4 = id & 31;
        uint32_t soff = sbase + (uint32_t)(m * PAD + k4 * 4) * 4u;
        asm volatile("cp.async.cg.shared.global [%0], [%1], 16;"
                     :: "r"(soff), "l"(g + (size_t)m * 512 + (size_t)k4 * 16)
                     : "memory");
    }
}

__global__ void __launch_bounds__(256, 1)
gemm_kernel(const float* __restrict__ A, float* __restrict__ out, int n_tiles) {
    extern __shared__ float smem[];
    int tid  = threadIdx.x;
    int wid  = tid >> 5;
    int lane = tid & 31;
    int wm   = wid >> 2;          // 0..1  -> 64-row half
    int wn   = wid & 3;           // 0..3  -> 32-col quarter
    int r    = lane >> 2;         // fragment row group 0..7
    int c    = lane & 3;          // fragment col group 0..3

    float* A0 = smem;
    float* A1 = smem + ABUF_FLTS;
    float* Bs = smem + 2 * ABUF_FLTS;
    uint32_t a0base = smem_u32(A0);
    uint32_t a1base = smem_u32(A1);

    // Stage B (already transposed [f][d]) into padded SMEM rows.
    for (int i = tid; i < 4096; i += 256) {            // i indexes float4
        int f  = i >> 5;
        int k4 = i & 31;
        float4 v = ((const float4*)g_B)[i];
        *(float4*)(Bs + f * PAD + k4 * 4) = v;
    }

    int grid  = (int)gridDim.x;
    int tile0 = (int)blockIdx.x;

    // Prologue: fill both A buffers.
    issue_a(a0base, A, tile0, tid);
    asm volatile("cp.async.commit_group;" ::: "memory");
    if (tile0 + grid < n_tiles) issue_a(a1base, A, tile0 + grid, tid);
    asm volatile("cp.async.commit_group;" ::: "memory");

    int it = 0;
    for (int tile = tile0; tile < n_tiles; tile += grid, it++) {
        const float* Ab = (it & 1) ? A1 : A0;
        uint32_t abase  = (it & 1) ? a1base : a0base;

        asm volatile("cp.async.wait_group 1;" ::: "memory");
        __syncthreads();

        float acc[4][4][4];
        #pragma unroll
        for (int mf = 0; mf < 4; mf++)
            #pragma unroll
            for (int nf = 0; nf < 4; nf++)
                #pragma unroll
                for (int q = 0; q < 4; q++) acc[mf][nf][q] = 0.0f;

        #pragma unroll
        for (int k0 = 0; k0 < 128; k0 += 8) {
            uint32_t b[4][2];
            #pragma unroll
            for (int nf = 0; nf < 4; nf++) {
                int n = wn * 32 + nf * 8 + r;
                b[nf][0] = __float_as_uint(Bs[n * PAD + k0 + c]);       // exact +/-1
                b[nf][1] = __float_as_uint(Bs[n * PAD + k0 + 4 + c]);
            }
            #pragma unroll
            for (int mf = 0; mf < 4; mf++) {
                int m = wm * 64 + mf * 16 + r;
                uint32_t fa0 = f2tf32(Ab[m * PAD + k0 + c]);
                uint32_t fa1 = f2tf32(Ab[(m + 8) * PAD + k0 + c]);
                uint32_t fa2 = f2tf32(Ab[m * PAD + k0 + 4 + c]);
                uint32_t fa3 = f2tf32(Ab[(m + 8) * PAD + k0 + 4 + c]);
                #pragma unroll
                for (int nf = 0; nf < 4; nf++)
                    mma_tf32(acc[mf][nf], fa0, fa1, fa2, fa3, b[nf][0], b[nf][1]);
            }
        }

        __syncthreads();   // everyone done reading this A buffer

        int nt = tile + 2 * grid;
        if (nt < n_tiles) issue_a(abase, A, nt, tid);
        asm volatile("cp.async.commit_group;" ::: "memory");

        // Epilogue: streaming stores. c0,c1 at (row, col..col+1); c2,c3 at row+8.
        float* obase = out + ((size_t)tile * 128 + (size_t)(wm * 64)) * 128 + wn * 32;
        #pragma unroll
        for (int mf = 0; mf < 4; mf++) {
            #pragma unroll
            for (int nf = 0; nf < 4; nf++) {
                float* p = obase + (size_t)(mf * 16 + r) * 128 + nf * 8 + c * 2;
                __stcs((float2*)p,             make_float2(acc[mf][nf][0], acc[mf][nf][1]));
                __stcs((float2*)(p + 8 * 128), make_float2(acc[mf][nf][2], acc[mf][nf][3]));
            }
        }
    }
}

// ------------------------------ launch -------------------------------------

extern "C" void kernel_launch(void* const* d_in, const int* in_sizes, int n_in,
                              void* d_out, int out_size) {
    const float* A       = (const float*)d_in[0];
    const float* W       = (const float*)d_in[1];
    const int*   seed    = (const int*)d_in[2];
    const int*   istrain = (const int*)d_in[3];
    float* out = (float*)d_out;

    int N = in_sizes[0] / 128;
    int n_tiles = N / 128;                 // 8192

    wbin_kernel<<<64, 256>>>(W, seed, istrain);

    int sms = 148;
    cudaDeviceGetAttribute(&sms, cudaDevAttrMultiProcessorCount, 0);
    if (sms > n_tiles) sms = n_tiles;

    cudaFuncSetAttribute(gemm_kernel, cudaFuncAttributeMaxDynamicSharedMemorySize, SMEM_TOTAL);
    gemm_kernel<<<sms, 256, SMEM_TOTAL>>>(A, out, n_tiles);
}